// round 13
// baseline (speedup 1.0000x reference)
#include <cuda_runtime.h>
#include <math.h>
#include <stdint.h>

#define B_  4
#define T_  2048
#define C_  1024
#define NH_ 16
#define HD_ 64
#define M_  (B_*T_)          // 8192
#define BH_ (B_*NH_)         // 64

#if defined(__CUDA_ARCH__) && (defined(__CUDA_ARCH_FEAT_SM103_ALL) || defined(__CUDA_ARCH_FEAT_SM100_ALL))
#define HAS_TCGEN05 1
#else
#define HAS_TCGEN05 0
#endif

// Scratch (allocation-free: device globals).
__device__ float g_q[(size_t)BH_*T_*HD_];
__device__ float g_k[(size_t)BH_*T_*HD_];
__device__ float g_v[(size_t)BH_*T_*HD_];    // fallback path only
__device__ float g_vT[(size_t)BH_*HD_*T_];   // [bh][d][t], tf32-rounded (tcgen05 path)
__device__ float g_y[(size_t)M_*C_];
__device__ float g_xr[(size_t)M_*C_];        // tf32-rounded x
__device__ float g_wqkvT[(size_t)3072*1024]; // W_qkv^T, tf32-rounded, [N][K]
__device__ float g_wprojT[(size_t)1024*1024];// W_proj^T, tf32-rounded, [N][K]

__device__ __forceinline__ float tf32r(float x) {
    float y; asm("cvt.rna.tf32.f32 %0, %1;" : "=f"(y) : "f"(x)); return y;
}

// GEMM smem (BN=256): [0:4) tmem ptr, [16,24) mbars,
// [1024:) 2 stages x (A 16KB + B 32KB) = 97.3KB -> 2 CTAs/SM
#define GEMM_STAGE  49152
#define GEMM_SMEM   (1024 + 2*GEMM_STAGE)
// ATTN smem: ctrl 1KB | Q 32KB | K 16KB | VT 16KB | P 32KB
#define ATTN_SMEM_T (1024 + 32768 + 16384 + 16384 + 32768)

#if HAS_TCGEN05
// ---------------------------------------------------------------------------
// PTX helpers (sm_103a only)
// ---------------------------------------------------------------------------
__device__ __forceinline__ uint32_t smem_u32(const void* p) {
    uint32_t a;
    asm("{ .reg .u64 t; cvta.to.shared.u64 t, %1; cvt.u32.u64 %0, t; }" : "=r"(a) : "l"(p));
    return a;
}
__device__ __forceinline__ uint32_t elect_one() {
    uint32_t p;
    asm volatile("{\n\t.reg .pred p;\n\telect.sync _|p, 0xFFFFFFFF;\n\tselp.b32 %0,1,0,p;\n\t}" : "=r"(p));
    return p;
}

#define MBARRIER_INIT(addr, cnt) \
    asm volatile("mbarrier.init.shared.b64 [%0], %1;" :: "r"((uint32_t)(addr)), "r"((uint32_t)(cnt)) : "memory")

#define MBARRIER_WAIT_PARITY(addr, par) do { \
    uint32_t _m = (uint32_t)(addr); uint32_t _p = (uint32_t)(par); uint32_t _d; \
    asm volatile("{\n\t.reg .pred p;\n\t" \
        "mbarrier.try_wait.parity.acquire.cta.shared::cta.b64 p, [%1], %2;\n\t" \
        "selp.b32 %0,1,0,p;\n\t}" : "=r"(_d) : "r"(_m), "r"(_p) : "memory"); \
    if (!_d) { \
        asm volatile("{\n\t.reg .pred P1;\n\t" \
            "WAIT_LOOP_%=:\n\t" \
            "mbarrier.try_wait.parity.acquire.cta.shared::cta.b64 P1, [%0], %1, 0x989680;\n\t" \
            "@P1 bra.uni WAIT_DONE_%=;\n\t" \
            "bra.uni WAIT_LOOP_%=;\n\t" \
            "WAIT_DONE_%=:\n\t}" :: "r"(_m), "r"(_p) : "memory"); \
    } \
} while (0)

#define TCGEN05_ALLOC(smem_addr, ncols) \
    asm volatile("tcgen05.alloc.cta_group::1.sync.aligned.shared::cta.b32 [%0], %1;" \
        :: "r"((uint32_t)(smem_addr)), "r"((uint32_t)(ncols)) : "memory")
#define TCGEN05_DEALLOC(tmem, ncols) \
    asm volatile("tcgen05.dealloc.cta_group::1.sync.aligned.b32 %0, %1;" :: "r"(tmem), "r"((uint32_t)(ncols)))
#define TCGEN05_RELINQ() \
    asm volatile("tcgen05.relinquish_alloc_permit.cta_group::1.sync.aligned;")
#define TCGEN05_COMMIT(mbar) \
    asm volatile("tcgen05.commit.cta_group::1.mbarrier::arrive::one.shared::cluster.b64 [%0];" \
        :: "r"((uint32_t)(mbar)) : "memory")
#define TCGEN05_FENCE_AFTER() \
    asm volatile("tcgen05.fence::after_thread_sync;" ::: "memory")
#define TCGEN05_WAIT_LD() \
    asm volatile("tcgen05.wait::ld.sync.aligned;" ::: "memory")
#define FENCE_ASYNC_SHARED() \
    asm volatile("fence.proxy.async.shared::cta;" ::: "memory")

#define TCGEN05_LD_X32(r, addr) \
    asm volatile("tcgen05.ld.sync.aligned.32x32b.x32.b32 " \
        "{%0,%1,%2,%3,%4,%5,%6,%7,%8,%9,%10,%11,%12,%13,%14,%15," \
        "%16,%17,%18,%19,%20,%21,%22,%23,%24,%25,%26,%27,%28,%29,%30,%31}, [%32];" \
        : "=r"((r)[0]),"=r"((r)[1]),"=r"((r)[2]),"=r"((r)[3]),"=r"((r)[4]),"=r"((r)[5]),"=r"((r)[6]),"=r"((r)[7]), \
          "=r"((r)[8]),"=r"((r)[9]),"=r"((r)[10]),"=r"((r)[11]),"=r"((r)[12]),"=r"((r)[13]),"=r"((r)[14]),"=r"((r)[15]), \
          "=r"((r)[16]),"=r"((r)[17]),"=r"((r)[18]),"=r"((r)[19]),"=r"((r)[20]),"=r"((r)[21]),"=r"((r)[22]),"=r"((r)[23]), \
          "=r"((r)[24]),"=r"((r)[25]),"=r"((r)[26]),"=r"((r)[27]),"=r"((r)[28]),"=r"((r)[29]),"=r"((r)[30]),"=r"((r)[31]) \
        : "r"(addr))

__device__ __forceinline__ void cp_async16(uint32_t saddr, const void* gptr) {
    asm volatile("{\n\t.reg .u64 g;\n\tcvta.to.global.u64 g, %1;\n\t"
                 "cp.async.cg.shared.global [%0], [g], 16;\n\t}"
                 :: "r"(saddr), "l"(gptr) : "memory");
}
#define CP_COMMIT() asm volatile("cp.async.commit_group;" ::: "memory")
#define CP_WAIT0()  asm volatile("cp.async.wait_group 0;" ::: "memory")

__device__ __forceinline__ uint64_t make_desc_sw128(uint32_t base) {
    const uint64_t BASE = (uint64_t(2) << 61) | (uint64_t(1) << 46) |
                          (uint64_t(64) << 32) | (uint64_t(1) << 16);
    return BASE | ((uint64_t)(base >> 4) & 0x3FFF);
}

__device__ __forceinline__ void mma_tf32_ss(uint32_t d, uint64_t ad, uint64_t bd,
                                            uint32_t idesc, uint32_t enable) {
    asm volatile(
        "{\n\t.reg .pred p;\n\tsetp.ne.u32 p, %5, 0;\n\t"
        "tcgen05.mma.cta_group::1.kind::tf32 [%0], %1, %2, %3, {%4,%4,%4,%4}, p;\n\t}"
        :: "r"(d), "l"(ad), "l"(bd), "r"(idesc), "r"(0u), "r"(enable) : "memory");
}

// idesc: dtype=F32(1)@[4:5], atype=TF32(2)@[7:9], btype=TF32(2)@[10:12],
//        N/8@[17:23), M/16@[24:28]
#define IDESC_G256 ((1u<<4) | (2u<<7) | (2u<<10) | (32u<<17) | (8u<<24))   // 128x256
#define IDESC_ATT  ((1u<<4) | (2u<<7) | (2u<<10) | ( 8u<<17) | (8u<<24))   // 128x64

__device__ __forceinline__ uint32_t sw128(uint32_t off) { return off ^ ((off >> 3) & 0x70); }

// Issue cp.async loads: A-tile 128x32 + B-tile 256x32, both K-major SW128.
__device__ __forceinline__ void issue_tile_loads(
    const float* __restrict__ A, const float* __restrict__ Wt,
    int bm, int bn, int k0, uint32_t stage_base, int tid)
{
    const int r = tid >> 3, c4 = (tid & 7) * 4;
#pragma unroll
    for (int p = 0; p < 4; p++) {
        uint32_t off = sw128((uint32_t)(r + p * 32) * 128 + c4 * 4);
        cp_async16(stage_base + off, &A[(size_t)(bm + r + p * 32) * 1024 + k0 + c4]);
    }
#pragma unroll
    for (int p = 0; p < 8; p++) {
        uint32_t off = sw128((uint32_t)(r + p * 32) * 128 + c4 * 4);
        cp_async16(stage_base + 16384 + off, &Wt[(size_t)(bn + r + p * 32) * 1024 + k0 + c4]);
    }
}

// 2-stage cp.async pipelined tf32 GEMM (BN=256), MMA-first ordering.
// Result: 128x256 fp32 in TMEM cols [0,256).
__device__ __forceinline__ void gemm_mainloop_tf32(
    const float* __restrict__ A, const float* __restrict__ Wt,
    int bm, int bn, uint32_t smb, uint32_t tmem)
{
    const int tid = threadIdx.x;
    const uint32_t st_base = smb + 1024;

    issue_tile_loads(A, Wt, bm, bn, 0, st_base, tid);
    CP_COMMIT();
    CP_WAIT0();
    __syncthreads();
    FENCE_ASYNC_SHARED();

#pragma unroll
    for (int i = 0; i < 32; i++) {
        // a) MMA(i) on stage i%2 (resident + fenced); overlaps everything below
        if (tid < 32 && elect_one()) {
            const uint32_t sb = st_base + (i % 2) * GEMM_STAGE;
            uint64_t ad = make_desc_sw128(sb);
            uint64_t bd = make_desc_sw128(sb + 16384);
#pragma unroll
            for (int s = 0; s < 4; s++)
                mma_tf32_ss(tmem, ad + s * 2, bd + s * 2, IDESC_G256,
                            (i > 0 || s > 0) ? 1u : 0u);
            TCGEN05_COMMIT(smb + 16 + (i % 2) * 8);
        }
        // b) refill stage (i+1)%2 (consumed by MMA(i-1)) with loads(i+1)
        if (i + 1 <= 31) {
            if (i >= 1)
                MBARRIER_WAIT_PARITY(smb + 16 + ((i - 1) % 2) * 8,
                                     (uint32_t)(((i - 1) / 2) & 1));
            issue_tile_loads(A, Wt, bm, bn, (i + 1) * 32,
                             st_base + ((i + 1) % 2) * GEMM_STAGE, tid);
            CP_COMMIT();
            CP_WAIT0();          // overlaps the running MMA(i)
        }
        __syncthreads();
        FENCE_ASYNC_SHARED();
    }
    // final: MMA(31) on mbar1, commit index 15 -> parity 1
    MBARRIER_WAIT_PARITY(smb + 16 + 8, 1);
    TCGEN05_FENCE_AFTER();
}
#endif  // HAS_TCGEN05

// ---------------------------------------------------------------------------
// Prep kernels
// ---------------------------------------------------------------------------
__global__ __launch_bounds__(256)
void round_x_kernel(const float* __restrict__ in, float* __restrict__ out, int n4)
{
    int i = blockIdx.x * 256 + threadIdx.x;
    if (i < n4) {
        float4 v = ((const float4*)in)[i];
        v.x = tf32r(v.x); v.y = tf32r(v.y); v.z = tf32r(v.z); v.w = tf32r(v.w);
        ((float4*)out)[i] = v;
    }
}

// in[K][N] row-major -> out[N][K] row-major, tf32-rounded. 32x32 tiles, 256 thr.
__global__ __launch_bounds__(256)
void transpose_round_kernel(const float* __restrict__ in, float* __restrict__ out,
                            int K, int N)
{
    __shared__ float tile[32][33];
    const int k0 = blockIdx.y * 32, n0 = blockIdx.x * 32;
    const int tx = threadIdx.x & 31, ty = threadIdx.x >> 5;
#pragma unroll
    for (int p = 0; p < 4; p++)
        tile[ty + p * 8][tx] = in[(size_t)(k0 + ty + p * 8) * N + n0 + tx];
    __syncthreads();
#pragma unroll
    for (int p = 0; p < 4; p++)
        out[(size_t)(n0 + ty + p * 8) * K + k0 + tx] = tf32r(tile[tx][ty + p * 8]);
}

// ---------------------------------------------------------------------------
// Fallback SIMT GEMM mainloop (compile-only on non-'a' targets).
// ---------------------------------------------------------------------------
__device__ __forceinline__ void gemm_mainloop_simt(
    const float* __restrict__ A, const float* __restrict__ W, int N,
    int bm, int bn, char* smem, float acc[8][8])
{
    float (*As)[32]  = (float (*)[32])(smem);
    float (*Bs)[128] = (float (*)[128])(smem + 128 * 32 * 4);
    const int tid = threadIdx.x;
    const int tx = tid & 15, ty = tid >> 4;

    for (int k0 = 0; k0 < 1024; k0 += 32) {
        __syncthreads();
        {
            int r = tid >> 3, c = (tid & 7) * 4;
#pragma unroll
            for (int p = 0; p < 4; p++) {
                float4 v = *(const float4*)&A[(size_t)(bm + r + p * 32) * 1024 + k0 + c];
                *(float4*)&As[r + p * 32][c] = v;
            }
        }
        {
            int r = tid >> 5, c = (tid & 31) * 4;
#pragma unroll
            for (int p = 0; p < 4; p++) {
                float4 v = *(const float4*)&W[(size_t)(k0 + r + p * 8) * N + bn + c];
                *(float4*)&Bs[r + p * 8][c] = v;
            }
        }
        __syncthreads();
#pragma unroll
        for (int k = 0; k < 32; k++) {
            float a[8], b[8];
#pragma unroll
            for (int i = 0; i < 8; i++) a[i] = As[ty * 8 + i][k];
            float4 b0 = *(float4*)&Bs[k][tx * 8];
            float4 b1 = *(float4*)&Bs[k][tx * 8 + 4];
            b[0] = b0.x; b[1] = b0.y; b[2] = b0.z; b[3] = b0.w;
            b[4] = b1.x; b[5] = b1.y; b[6] = b1.z; b[7] = b1.w;
#pragma unroll
            for (int i = 0; i < 8; i++)
#pragma unroll
                for (int j = 0; j < 8; j++) acc[i][j] += a[i] * b[j];
        }
    }
}

// ---------------------------------------------------------------------------
// Kernel A: QKV GEMM + bias + per-head affine scatter
// ---------------------------------------------------------------------------
__device__ __forceinline__ void qkv_store_one(
    int b, int t, int n, float v,
    const float* __restrict__ q_scale, const float* __restrict__ q_bias,
    const float* __restrict__ k_scale, const float* __restrict__ k_bias)
{
    int sect = n >> 10, c = n & 1023;
    int h = c >> 6, d = c & 63;
    size_t idx = ((size_t)(b * NH_ + h) * T_ + t) * HD_ + d;
#if HAS_TCGEN05
    // Q/K/V all feed tf32 MMAs: round here (rna). V goes straight to g_vT.
    if (sect == 0)      g_q[idx] = tf32r(v * q_scale[c] + q_bias[c]);
    else if (sect == 1) g_k[idx] = tf32r(v * k_scale[c] + k_bias[c]);
    else                g_vT[((size_t)(b * NH_ + h) * HD_ + d) * T_ + t] = tf32r(v);
#else
    if (sect == 0)      g_q[idx] = v * q_scale[c] + q_bias[c];
    else if (sect == 1) g_k[idx] = v * k_scale[c] + k_bias[c];
    else                g_v[idx] = v;
#endif
}

__global__ __launch_bounds__(256)
void qkv_gemm_kernel(const float* __restrict__ X, const float* __restrict__ W,
                     const float* __restrict__ bias,
                     const float* __restrict__ q_scale, const float* __restrict__ q_bias,
                     const float* __restrict__ k_scale, const float* __restrict__ k_bias)
{
    extern __shared__ char smem[];
    const int bm = blockIdx.y * 128, bn = blockIdx.x * 256;
    const int tid = threadIdx.x;

#if HAS_TCGEN05
    uint32_t smb = smem_u32(smem);
    const int wid = tid >> 5, lid = tid & 31;
    if (wid == 0) {
        TCGEN05_ALLOC(smb, 256);
        TCGEN05_RELINQ();   // release alloc permit immediately (occupancy!)
    }
    if (tid == 0) { MBARRIER_INIT(smb + 16, 1); MBARRIER_INIT(smb + 24, 1); }
    __syncthreads();
    uint32_t tmem;
    asm volatile("ld.shared.b32 %0, [%1];" : "=r"(tmem) : "r"(smb));

    gemm_mainloop_tf32(g_xr, g_wqkvT, bm, bn, smb, tmem);

    if (wid < 4) {
        const int m = bm + wid * 32 + lid;
        const int b = m >> 11, t = m & 2047;
        const uint32_t woff = ((uint32_t)wid << 21);
#pragma unroll
        for (int chunk = 0; chunk < 8; chunk++) {
            uint32_t r[32];
            TCGEN05_LD_X32(r, tmem + chunk * 32 + woff);
            TCGEN05_WAIT_LD();
#pragma unroll
            for (int j = 0; j < 32; j++) {
                int n = bn + chunk * 32 + j;
                float v = __uint_as_float(r[j]) + bias[n];
                qkv_store_one(b, t, n, v, q_scale, q_bias, k_scale, k_bias);
            }
        }
    }
    __syncthreads();
    if (wid == 0) TCGEN05_DEALLOC(tmem, 256);
    (void)X; (void)W;
#else
    const int tx = tid & 15, ty = tid >> 4;
    for (int half = 0; half < 2; half++) {
        int bn_h = bn + half * 128;
        float acc[8][8];
#pragma unroll
        for (int i = 0; i < 8; i++)
#pragma unroll
            for (int j = 0; j < 8; j++) acc[i][j] = 0.f;
        gemm_mainloop_simt(X, W, 3072, bm, bn_h, smem, acc);
#pragma unroll
        for (int i = 0; i < 8; i++) {
            int m = bm + ty * 8 + i;
            int b = m >> 11, t = m & 2047;
#pragma unroll
            for (int j = 0; j < 8; j++) {
                int n = bn_h + tx * 8 + j;
                qkv_store_one(b, t, n, acc[i][j] + bias[n], q_scale, q_bias, k_scale, k_bias);
            }
        }
        __syncthreads();
    }
#endif
}

// ---------------------------------------------------------------------------
// Kernel C: projection GEMM + bias -> out
// ---------------------------------------------------------------------------
__global__ __launch_bounds__(256)
void proj_gemm_kernel(const float* __restrict__ W, const float* __restrict__ bias,
                      float* __restrict__ out)
{
    extern __shared__ char smem[];
    const int bm = blockIdx.y * 128, bn = blockIdx.x * 256;
    const int tid = threadIdx.x;

#if HAS_TCGEN05
    uint32_t smb = smem_u32(smem);
    const int wid = tid >> 5, lid = tid & 31;
    if (wid == 0) {
        TCGEN05_ALLOC(smb, 256);
        TCGEN05_RELINQ();
    }
    if (tid == 0) { MBARRIER_INIT(smb + 16, 1); MBARRIER_INIT(smb + 24, 1); }
    __syncthreads();
    uint32_t tmem;
    asm volatile("ld.shared.b32 %0, [%1];" : "=r"(tmem) : "r"(smb));

    gemm_mainloop_tf32(g_y, g_wprojT, bm, bn, smb, tmem);

    if (wid < 4) {
        const int m = bm + wid * 32 + lid;
        const uint32_t woff = ((uint32_t)wid << 21);
#pragma unroll
        for (int chunk = 0; chunk < 8; chunk++) {
            uint32_t r[32];
            TCGEN05_LD_X32(r, tmem + chunk * 32 + woff);
            TCGEN05_WAIT_LD();
#pragma unroll
            for (int j = 0; j < 32; j++) {
                int n = bn + chunk * 32 + j;
                out[(size_t)m * 1024 + n] = __uint_as_float(r[j]) + bias[n];
            }
        }
    }
    __syncthreads();
    if (wid == 0) TCGEN05_DEALLOC(tmem, 256);
    (void)W;
#else
    const int tx = tid & 15, ty = tid >> 4;
    for (int half = 0; half < 2; half++) {
        int bn_h = bn + half * 128;
        float acc[8][8];
#pragma unroll
        for (int i = 0; i < 8; i++)
#pragma unroll
            for (int j = 0; j < 8; j++) acc[i][j] = 0.f;
        gemm_mainloop_simt(g_y, W, 1024, bm, bn_h, smem, acc);
#pragma unroll
        for (int i = 0; i < 8; i++) {
            int m = bm + ty * 8 + i;
#pragma unroll
            for (int j = 0; j < 8; j++) {
                int n = bn_h + tx * 8 + j;
                out[(size_t)m * 1024 + n] = acc[i][j] + bias[n];
            }
        }
        __syncthreads();
    }
#endif
}

// ---------------------------------------------------------------------------
// Kernel B: causal flash attention — tcgen05 tf32 with K/V prefetch.
// CTA = 128 Q-rows x (b,h). 128 threads. grid (16, 64).
// TMEM: S cols 0-63, O_partial cols 64-127.
// ---------------------------------------------------------------------------
__global__ __launch_bounds__(128)
void attn_kernel()
{
#if HAS_TCGEN05
    extern __shared__ char smem[];
    uint32_t smb = smem_u32(smem);
    const int tid = threadIdx.x, wid = tid >> 5, lid = tid & 31;
    const int qt = gridDim.x - 1 - blockIdx.x;   // long CTAs first
    const int bh = blockIdx.y;

    const float* Qg  = g_q  + (size_t)bh * T_ * HD_;
    const float* Kg  = g_k  + (size_t)bh * T_ * HD_;
    const float* VTg = g_vT + (size_t)bh * HD_ * T_;

    const uint32_t Qb = smb + 1024;
    const uint32_t Kb = Qb + 32768;
    const uint32_t Vb = Kb + 16384;
    const uint32_t Pb = Vb + 16384;

    if (wid == 0) {
        TCGEN05_ALLOC(smb, 128);
        TCGEN05_RELINQ();
    }
    if (tid == 0) MBARRIER_INIT(smb + 16, 1);
    __syncthreads();
    uint32_t tmem;
    asm volatile("ld.shared.b32 %0, [%1];" : "=r"(tmem) : "r"(smb));

    // Q tile (128x64) -> 2 K-major chunks of 128x32, SW128
    for (int i = tid; i < 2048; i += 128) {
        int c = i >> 10, rem = i & 1023, r = rem >> 3, seg = rem & 7;
        cp_async16(Qb + c * 16384 + sw128((uint32_t)r * 128 + seg * 16),
                   Qg + (size_t)(qt * 128 + r) * 64 + c * 32 + seg * 4);
    }
    CP_COMMIT();

    const int m = wid * 32 + lid;
    const int q_glob = qt * 128 + m;
    const uint32_t woff = ((uint32_t)wid << 21);

    float O[64];
#pragma unroll
    for (int j = 0; j < 64; j++) O[j] = 0.f;
    float mrow = -INFINITY, lrow = 0.f;

    int ph = 0;
    const int nkt = 2 * qt + 2;

    // prefetch K(0), V(0)
    for (int i = tid; i < 1024; i += 128) {
        int c = i >> 9, rem = i & 511, r = rem >> 3, seg = rem & 7;
        uint32_t off = sw128((uint32_t)r * 128 + seg * 16);
        cp_async16(Kb + c * 8192 + off, Kg + (size_t)r * 64 + c * 32 + seg * 4);
        cp_async16(Vb + c * 8192 + off, VTg + (size_t)r * T_ + c * 32 + seg * 4);
    }
    CP_COMMIT();

    for (int kt = 0; kt < nkt; kt++) {
        CP_WAIT0();              // Q (first iter) + K(kt) + V(kt) resident
        __syncthreads();

        // S = Q K^T  (M=128, N=64, K=64)
        if (wid == 0 && elect_one()) {
#pragma unroll
            for (int c = 0; c < 2; c++) {
                uint64_t ad = make_desc_sw128(Qb + c * 16384);
                uint64_t bd = make_desc_sw128(Kb + c * 8192);
#pragma unroll
                for (int s = 0; s < 4; s++)
                    mma_tf32_ss(tmem, ad + s * 2, bd + s * 2, IDESC_ATT,
                                (c > 0 || s > 0) ? 1u : 0u);
            }
            TCGEN05_COMMIT(smb + 16);
        }
        MBARRIER_WAIT_PARITY(smb + 16, (uint32_t)(ph & 1)); ph++;
        TCGEN05_FENCE_AFTER();

        // K buffer free: prefetch K(kt+1) under softmax/PV
        if (kt + 1 < nkt) {
            for (int i = tid; i < 1024; i += 128) {
                int c = i >> 9, rem = i & 511, r = rem >> 3, seg = rem & 7;
                cp_async16(Kb + c * 8192 + sw128((uint32_t)r * 128 + seg * 16),
                           Kg + (size_t)((kt + 1) * 64 + r) * 64 + c * 32 + seg * 4);
            }
        }
        CP_COMMIT();

        // read S row, softmax in-lane (no shuffles)
        float sv[64];
        {
            uint32_t r0[32], r1[32];
            TCGEN05_LD_X32(r0, tmem + woff);
            TCGEN05_LD_X32(r1, tmem + 32 + woff);
            TCGEN05_WAIT_LD();
#pragma unroll
            for (int j = 0; j < 32; j++) { sv[j] = __uint_as_float(r0[j]); sv[32 + j] = __uint_as_float(r1[j]); }
        }
        const bool diag = (kt >= 2 * qt);
        float mt = -INFINITY;
#pragma unroll
        for (int j = 0; j < 64; j++) {
            float v = sv[j] * 0.125f;
            if (diag && (kt * 64 + j > q_glob)) v = -INFINITY;
            sv[j] = v;
            mt = fmaxf(mt, v);
        }
        float mn = fmaxf(mrow, mt);
        float rscale = __expf(mrow - mn);
        mrow = mn;
        float rs = 0.f;
#pragma unroll
        for (int j = 0; j < 64; j++) { float p = __expf(sv[j] - mn); sv[j] = p; rs += p; }
        lrow = lrow * rscale + rs;

        // P -> smem, K-major 2 chunks of 128x32, tf32-rounded
#pragma unroll
        for (int j = 0; j < 64; j += 4) {
            float4 p4;
            p4.x = tf32r(sv[j]); p4.y = tf32r(sv[j + 1]);
            p4.z = tf32r(sv[j + 2]); p4.w = tf32r(sv[j + 3]);
            uint32_t c = (uint32_t)(j >> 5);
            uint32_t addr = Pb + c * 16384 + sw128((uint32_t)m * 128 + (uint32_t)(j & 31) * 4);
            asm volatile("st.shared.v4.b32 [%0], {%1,%2,%3,%4};"
                         :: "r"(addr), "r"(__float_as_uint(p4.x)), "r"(__float_as_uint(p4.y)),
                            "r"(__float_as_uint(p4.z)), "r"(__float_as_uint(p4.w)) : "memory");
        }
        FENCE_ASYNC_SHARED();
        __syncthreads();

        // O_partial = P V  (M=128, N=64(d), K=64(kpos))
        if (wid == 0 && elect_one()) {
#pragma unroll
            for (int c = 0; c < 2; c++) {
                uint64_t ad = make_desc_sw128(Pb + c * 16384);
                uint64_t bd = make_desc_sw128(Vb + c * 8192);
#pragma unroll
                for (int s = 0; s < 4; s++)
                    mma_tf32_ss(tmem + 64, ad + s * 2, bd + s * 2, IDESC_ATT,
                                (c > 0 || s > 0) ? 1u : 0u);
            }
            TCGEN05_COMMIT(smb + 16);
        }
        MBARRIER_WAIT_PARITY(smb + 16, (uint32_t)(ph & 1)); ph++;
        TCGEN05_FENCE_AFTER();

        // V buffer free: prefetch V(kt+1) under accumulate
        if (kt + 1 < nkt) {
            for (int i = tid; i < 1024; i += 128) {
                int c = i >> 9, rem = i & 511, r = rem >> 3, seg = rem & 7;
                cp_async16(Vb + c * 8192 + sw128((uint32_t)r * 128 + seg * 16),
                           VTg + (size_t)r * T_ + (kt + 1) * 64 + c * 32 + seg * 4);
            }
        }
        CP_COMMIT();

        {
            uint32_t r0[32], r1[32];
            TCGEN05_LD_X32(r0, tmem + 64 + woff);
            TCGEN05_LD_X32(r1, tmem + 96 + woff);
            TCGEN05_WAIT_LD();
#pragma unroll
            for (int j = 0; j < 32; j++) {
                O[j]      = O[j]      * rscale + __uint_as_float(r0[j]);
                O[32 + j] = O[32 + j] * rscale + __uint_as_float(r1[j]);
            }
        }
        __syncthreads();
    }

    // write O/l to g_y [B,T,C], tf32-rounded (feeds proj A)
    {
        const int b = bh >> 4, h = bh & 15;
        const int t = qt * 128 + m;
        float inv = 1.f / lrow;
        float* dst = &g_y[((size_t)(b * T_ + t)) * C_ + h * 64];
#pragma unroll
        for (int j = 0; j < 64; j += 4) {
            float4 o4;
            o4.x = tf32r(O[j] * inv);     o4.y = tf32r(O[j + 1] * inv);
            o4.z = tf32r(O[j + 2] * inv); o4.w = tf32r(O[j + 3] * inv);
            *(float4*)(dst + j) = o4;
        }
    }
    __syncthreads();
    if (wid == 0) TCGEN05_DEALLOC(tmem, 128);
#else
    // Fallback: correct SIMT flash attention, 128 threads, 1 q-row per thread.
    __shared__ float Ks[64][65];
    __shared__ float Vs[64][65];
    const int tid = threadIdx.x;
    const int qt = gridDim.x - 1 - blockIdx.x;
    const int bh = blockIdx.y;
    const int t = qt * 128 + tid;
    const float* Qg = g_q + (size_t)bh * T_ * HD_;
    const float* Kg = g_k + (size_t)bh * T_ * HD_;
    const float* Vg = g_v + (size_t)bh * T_ * HD_;

    float q[64], O[64];
#pragma unroll
    for (int d = 0; d < 64; d++) { q[d] = Qg[(size_t)t * 64 + d]; O[d] = 0.f; }
    float mrow = -INFINITY, lrow = 0.f;

    for (int kt = 0; kt < 2 * qt + 2; kt++) {
        __syncthreads();
        for (int i = tid; i < 64 * 64; i += 128) {
            int r = i >> 6, c = i & 63;
            Ks[r][c] = Kg[(size_t)(kt * 64 + r) * 64 + c];
            Vs[r][c] = Vg[(size_t)(kt * 64 + r) * 64 + c];
        }
        __syncthreads();
        for (int kk = 0; kk < 64; kk++) {
            int kg = kt * 64 + kk;
            if (kg > t) break;
            float s = 0.f;
#pragma unroll
            for (int d = 0; d < 64; d++) s += q[d] * Ks[kk][d];
            s *= 0.125f;
            float mn = fmaxf(mrow, s);
            float rscale = expf(mrow - mn);
            float p = expf(s - mn);
            lrow = lrow * rscale + p;
            mrow = mn;
#pragma unroll
            for (int d = 0; d < 64; d++) O[d] = O[d] * rscale + p * Vs[kk][d];
        }
    }
    const int b = bh >> 4, h = bh & 15;
    float inv = 1.f / lrow;
#pragma unroll
    for (int d = 0; d < 64; d++)
        g_y[((size_t)(b * T_ + t)) * C_ + h * 64 + d] = O[d] * inv;
#endif
}

// ---------------------------------------------------------------------------
extern "C" void kernel_launch(void* const* d_in, const int* in_sizes, int n_in,
                              void* d_out, int out_size)
{
    const float* x     = (const float*)d_in[0];
    const float* Wqkv  = (const float*)d_in[1];
    const float* bqkv  = (const float*)d_in[2];
    const float* Wproj = (const float*)d_in[3];
    const float* bproj = (const float*)d_in[4];
    const float* qsc   = (const float*)d_in[5];
    const float* qbi   = (const float*)d_in[6];
    const float* ksc   = (const float*)d_in[7];
    const float* kbi   = (const float*)d_in[8];
    float* out = (float*)d_out;
    (void)in_sizes; (void)n_in; (void)out_size;

    cudaFuncSetAttribute(qkv_gemm_kernel, cudaFuncAttributeMaxDynamicSharedMemorySize, GEMM_SMEM);
    cudaFuncSetAttribute(proj_gemm_kernel, cudaFuncAttributeMaxDynamicSharedMemorySize, GEMM_SMEM);
    cudaFuncSetAttribute(attn_kernel, cudaFuncAttributeMaxDynamicSharedMemorySize, ATTN_SMEM_T);

    float* p_xr;     cudaGetSymbolAddress((void**)&p_xr,     g_xr);
    float* p_wqkvT;  cudaGetSymbolAddress((void**)&p_wqkvT,  g_wqkvT);
    float* p_wprojT; cudaGetSymbolAddress((void**)&p_wprojT, g_wprojT);

    round_x_kernel<<<(M_ * C_ / 4 + 255) / 256, 256>>>(x, p_xr, M_ * C_ / 4);
    {
        dim3 gt(3072 / 32, 1024 / 32);
        transpose_round_kernel<<<gt, 256>>>(Wqkv, p_wqkvT, 1024, 3072);
    }
    {
        dim3 gt(1024 / 32, 1024 / 32);
        transpose_round_kernel<<<gt, 256>>>(Wproj, p_wprojT, 1024, 1024);
    }

    dim3 g1(3072 / 256, M_ / 128);   // 12 x 64
    qkv_gemm_kernel<<<g1, 256, GEMM_SMEM>>>(x, Wqkv, bqkv, qsc, qbi, ksc, kbi);

    dim3 g2(T_ / 128, BH_);          // 16 x 64
    attn_kernel<<<g2, 128, ATTN_SMEM_T>>>();

    dim3 g3(1024 / 256, M_ / 128);   // 4 x 64
    proj_gemm_kernel<<<g3, 256, GEMM_SMEM>>>(Wproj, bproj, out);
}

// round 15
// speedup vs baseline: 1.1688x; 1.1688x over previous
#include <cuda_runtime.h>
#include <math.h>
#include <stdint.h>

#define B_  4
#define T_  2048
#define C_  1024
#define NH_ 16
#define HD_ 64
#define M_  (B_*T_)          // 8192
#define BH_ (B_*NH_)         // 64

#if defined(__CUDA_ARCH__) && (defined(__CUDA_ARCH_FEAT_SM103_ALL) || defined(__CUDA_ARCH_FEAT_SM100_ALL))
#define HAS_TCGEN05 1
#else
#define HAS_TCGEN05 0
#endif

// Scratch (allocation-free: device globals).
__device__ float g_q[(size_t)BH_*T_*HD_];
__device__ float g_k[(size_t)BH_*T_*HD_];
__device__ float g_v[(size_t)BH_*T_*HD_];    // fallback path only
__device__ float g_vT[(size_t)BH_*HD_*T_];   // [bh][d][t], tf32-rounded (tcgen05 path)
__device__ float g_y[(size_t)M_*C_];
__device__ float g_xr[(size_t)M_*C_];        // tf32-rounded x
__device__ float g_wqkvT[(size_t)3072*1024]; // W_qkv^T, tf32-rounded, [N][K]
__device__ float g_wprojT[(size_t)1024*1024];// W_proj^T, tf32-rounded, [N][K]

__device__ __forceinline__ float tf32r(float x) {
    float y; asm("cvt.rna.tf32.f32 %0, %1;" : "=f"(y) : "f"(x)); return y;
}

// GEMM smem (R12 config): [0:4) tmem ptr, [16,24,32) mbars,
// [1024:) 3 stages x (A 16KB + B 16KB) = 97.3KB -> 2 CTAs/SM
#define GEMM_SMEM (1024 + 3*32768)

// ATTN smem: Q 32KB | K 16KB | V 2x16KB | P 32KB | ctrl 128B = 114816 B
#define ATTN_Q   0
#define ATTN_K   32768
#define ATTN_V   49152
#define ATTN_P   81920
#define ATTN_CTL 114688
#define ATTN_SMEM_T (114688 + 128)

#if HAS_TCGEN05
// ---------------------------------------------------------------------------
// PTX helpers (sm_103a only)
// ---------------------------------------------------------------------------
__device__ __forceinline__ uint32_t smem_u32(const void* p) {
    uint32_t a;
    asm("{ .reg .u64 t; cvta.to.shared.u64 t, %1; cvt.u32.u64 %0, t; }" : "=r"(a) : "l"(p));
    return a;
}
__device__ __forceinline__ uint32_t elect_one() {
    uint32_t p;
    asm volatile("{\n\t.reg .pred p;\n\telect.sync _|p, 0xFFFFFFFF;\n\tselp.b32 %0,1,0,p;\n\t}" : "=r"(p));
    return p;
}

#define MBARRIER_INIT(addr, cnt) \
    asm volatile("mbarrier.init.shared.b64 [%0], %1;" :: "r"((uint32_t)(addr)), "r"((uint32_t)(cnt)) : "memory")

#define MBARRIER_WAIT_PARITY(addr, par) do { \
    uint32_t _m = (uint32_t)(addr); uint32_t _p = (uint32_t)(par); uint32_t _d; \
    asm volatile("{\n\t.reg .pred p;\n\t" \
        "mbarrier.try_wait.parity.acquire.cta.shared::cta.b64 p, [%1], %2;\n\t" \
        "selp.b32 %0,1,0,p;\n\t}" : "=r"(_d) : "r"(_m), "r"(_p) : "memory"); \
    if (!_d) { \
        asm volatile("{\n\t.reg .pred P1;\n\t" \
            "WAIT_LOOP_%=:\n\t" \
            "mbarrier.try_wait.parity.acquire.cta.shared::cta.b64 P1, [%0], %1, 0x989680;\n\t" \
            "@P1 bra.uni WAIT_DONE_%=;\n\t" \
            "bra.uni WAIT_LOOP_%=;\n\t" \
            "WAIT_DONE_%=:\n\t}" :: "r"(_m), "r"(_p) : "memory"); \
    } \
} while (0)

#define TCGEN05_ALLOC(smem_addr, ncols) \
    asm volatile("tcgen05.alloc.cta_group::1.sync.aligned.shared::cta.b32 [%0], %1;" \
        :: "r"((uint32_t)(smem_addr)), "r"((uint32_t)(ncols)) : "memory")
#define TCGEN05_DEALLOC(tmem, ncols) \
    asm volatile("tcgen05.dealloc.cta_group::1.sync.aligned.b32 %0, %1;" :: "r"(tmem), "r"((uint32_t)(ncols)))
#define TCGEN05_RELINQ() \
    asm volatile("tcgen05.relinquish_alloc_permit.cta_group::1.sync.aligned;")
#define TCGEN05_COMMIT(mbar) \
    asm volatile("tcgen05.commit.cta_group::1.mbarrier::arrive::one.shared::cluster.b64 [%0];" \
        :: "r"((uint32_t)(mbar)) : "memory")
#define TCGEN05_FENCE_AFTER() \
    asm volatile("tcgen05.fence::after_thread_sync;" ::: "memory")
#define TCGEN05_WAIT_LD() \
    asm volatile("tcgen05.wait::ld.sync.aligned;" ::: "memory")
#define FENCE_ASYNC_SHARED() \
    asm volatile("fence.proxy.async.shared::cta;" ::: "memory")

#define TCGEN05_LD_X32(r, addr) \
    asm volatile("tcgen05.ld.sync.aligned.32x32b.x32.b32 " \
        "{%0,%1,%2,%3,%4,%5,%6,%7,%8,%9,%10,%11,%12,%13,%14,%15," \
        "%16,%17,%18,%19,%20,%21,%22,%23,%24,%25,%26,%27,%28,%29,%30,%31}, [%32];" \
        : "=r"((r)[0]),"=r"((r)[1]),"=r"((r)[2]),"=r"((r)[3]),"=r"((r)[4]),"=r"((r)[5]),"=r"((r)[6]),"=r"((r)[7]), \
          "=r"((r)[8]),"=r"((r)[9]),"=r"((r)[10]),"=r"((r)[11]),"=r"((r)[12]),"=r"((r)[13]),"=r"((r)[14]),"=r"((r)[15]), \
          "=r"((r)[16]),"=r"((r)[17]),"=r"((r)[18]),"=r"((r)[19]),"=r"((r)[20]),"=r"((r)[21]),"=r"((r)[22]),"=r"((r)[23]), \
          "=r"((r)[24]),"=r"((r)[25]),"=r"((r)[26]),"=r"((r)[27]),"=r"((r)[28]),"=r"((r)[29]),"=r"((r)[30]),"=r"((r)[31]) \
        : "r"(addr))

__device__ __forceinline__ void cp_async16(uint32_t saddr, const void* gptr) {
    asm volatile("{\n\t.reg .u64 g;\n\tcvta.to.global.u64 g, %1;\n\t"
                 "cp.async.cg.shared.global [%0], [g], 16;\n\t}"
                 :: "r"(saddr), "l"(gptr) : "memory");
}
#define CP_COMMIT() asm volatile("cp.async.commit_group;" ::: "memory")
#define CP_WAIT1()  asm volatile("cp.async.wait_group 1;" ::: "memory")
#define CP_WAIT0()  asm volatile("cp.async.wait_group 0;" ::: "memory")

__device__ __forceinline__ uint64_t make_desc_sw128(uint32_t base) {
    const uint64_t BASE = (uint64_t(2) << 61) | (uint64_t(1) << 46) |
                          (uint64_t(64) << 32) | (uint64_t(1) << 16);
    return BASE | ((uint64_t)(base >> 4) & 0x3FFF);
}

__device__ __forceinline__ void mma_tf32_ss(uint32_t d, uint64_t ad, uint64_t bd,
                                            uint32_t idesc, uint32_t enable) {
    asm volatile(
        "{\n\t.reg .pred p;\n\tsetp.ne.u32 p, %5, 0;\n\t"
        "tcgen05.mma.cta_group::1.kind::tf32 [%0], %1, %2, %3, {%4,%4,%4,%4}, p;\n\t}"
        :: "r"(d), "l"(ad), "l"(bd), "r"(idesc), "r"(0u), "r"(enable) : "memory");
}

// idesc: dtype=F32(1)@[4:5], atype=TF32(2)@[7:9], btype=TF32(2)@[10:12],
//        N/8@[17:23), M/16@[24:28]
#define IDESC_TF32 ((1u<<4) | (2u<<7) | (2u<<10) | (16u<<17) | (8u<<24))   // 128x128
#define IDESC_ATT  ((1u<<4) | (2u<<7) | (2u<<10) | ( 8u<<17) | (8u<<24))   // 128x64

__device__ __forceinline__ uint32_t sw128(uint32_t off) { return off ^ ((off >> 3) & 0x70); }

// Issue cp.async loads for one 128x32 A-tile + 128x32 B-tile (both K-major).
__device__ __forceinline__ void issue_tile_loads(
    const float* __restrict__ A, const float* __restrict__ Wt,
    int bm, int bn, int k0, uint32_t stage_base, int tid)
{
    const int r = tid >> 3, c4 = (tid & 7) * 4;
#pragma unroll
    for (int p = 0; p < 4; p++) {
        uint32_t off = sw128((uint32_t)(r + p * 32) * 128 + c4 * 4);
        cp_async16(stage_base + off,         &A [(size_t)(bm + r + p * 32) * 1024 + k0 + c4]);
        cp_async16(stage_base + 16384 + off, &Wt[(size_t)(bn + r + p * 32) * 1024 + k0 + c4]);
    }
}

// 3-stage cp.async pipelined tf32 GEMM mainloop, MMA-first ordering (R12).
__device__ __forceinline__ void gemm_mainloop_tf32(
    const float* __restrict__ A, const float* __restrict__ Wt,
    int bm, int bn, uint32_t smb, uint32_t tmem)
{
    const int tid = threadIdx.x;
    const uint32_t st_base = smb + 1024;

    issue_tile_loads(A, Wt, bm, bn, 0, st_base, tid);             CP_COMMIT();
    issue_tile_loads(A, Wt, bm, bn, 32, st_base + 32768, tid);    CP_COMMIT();
    CP_WAIT1();
    __syncthreads();
    FENCE_ASYNC_SHARED();

#pragma unroll
    for (int i = 0; i < 32; i++) {
        if (tid < 32 && elect_one()) {
            const uint32_t sb = st_base + (i % 3) * 32768;
            uint64_t ad = make_desc_sw128(sb);
            uint64_t bd = make_desc_sw128(sb + 16384);
#pragma unroll
            for (int s = 0; s < 4; s++)
                mma_tf32_ss(tmem, ad + s * 2, bd + s * 2, IDESC_TF32,
                            (i > 0 || s > 0) ? 1u : 0u);
            TCGEN05_COMMIT(smb + 16 + (i % 3) * 8);
        }
        if (i + 2 <= 31) {
            if (i >= 1)
                MBARRIER_WAIT_PARITY(smb + 16 + ((i - 1) % 3) * 8,
                                     (uint32_t)(((i - 1) / 3) & 1));
            issue_tile_loads(A, Wt, bm, bn, (i + 2) * 32,
                             st_base + ((i + 2) % 3) * 32768, tid);
        }
        CP_COMMIT();
        CP_WAIT1();
        __syncthreads();
        FENCE_ASYNC_SHARED();
    }
    // MMA(31) on mbar[1]; 11th commit -> parity (31/3)&1 = 0
    MBARRIER_WAIT_PARITY(smb + 16 + 8, 0);
    TCGEN05_FENCE_AFTER();
}
#endif  // HAS_TCGEN05

// ---------------------------------------------------------------------------
// Prep kernels
// ---------------------------------------------------------------------------
__global__ __launch_bounds__(256)
void round_x_kernel(const float* __restrict__ in, float* __restrict__ out, int n4)
{
    int i = blockIdx.x * 256 + threadIdx.x;
    if (i < n4) {
        float4 v = ((const float4*)in)[i];
        v.x = tf32r(v.x); v.y = tf32r(v.y); v.z = tf32r(v.z); v.w = tf32r(v.w);
        ((float4*)out)[i] = v;
    }
}

// in[K][N] row-major -> out[N][K] row-major, tf32-rounded. 32x32 tiles, 256 thr.
__global__ __launch_bounds__(256)
void transpose_round_kernel(const float* __restrict__ in, float* __restrict__ out,
                            int K, int N)
{
    __shared__ float tile[32][33];
    const int k0 = blockIdx.y * 32, n0 = blockIdx.x * 32;
    const int tx = threadIdx.x & 31, ty = threadIdx.x >> 5;
#pragma unroll
    for (int p = 0; p < 4; p++)
        tile[ty + p * 8][tx] = in[(size_t)(k0 + ty + p * 8) * N + n0 + tx];
    __syncthreads();
#pragma unroll
    for (int p = 0; p < 4; p++)
        out[(size_t)(n0 + ty + p * 8) * K + k0 + tx] = tf32r(tile[tx][ty + p * 8]);
}

// ---------------------------------------------------------------------------
// Fallback SIMT GEMM mainloop (compile-only on non-'a' targets).
// ---------------------------------------------------------------------------
__device__ __forceinline__ void gemm_mainloop_simt(
    const float* __restrict__ A, const float* __restrict__ W, int N,
    int bm, int bn, char* smem, float acc[8][8])
{
    float (*As)[32]  = (float (*)[32])(smem);
    float (*Bs)[128] = (float (*)[128])(smem + 128 * 32 * 4);
    const int tid = threadIdx.x;
    const int tx = tid & 15, ty = tid >> 4;

    for (int k0 = 0; k0 < 1024; k0 += 32) {
        __syncthreads();
        {
            int r = tid >> 3, c = (tid & 7) * 4;
#pragma unroll
            for (int p = 0; p < 4; p++) {
                float4 v = *(const float4*)&A[(size_t)(bm + r + p * 32) * 1024 + k0 + c];
                *(float4*)&As[r + p * 32][c] = v;
            }
        }
        {
            int r = tid >> 5, c = (tid & 31) * 4;
#pragma unroll
            for (int p = 0; p < 4; p++) {
                float4 v = *(const float4*)&W[(size_t)(k0 + r + p * 8) * N + bn + c];
                *(float4*)&Bs[r + p * 8][c] = v;
            }
        }
        __syncthreads();
#pragma unroll
        for (int k = 0; k < 32; k++) {
            float a[8], b[8];
#pragma unroll
            for (int i = 0; i < 8; i++) a[i] = As[ty * 8 + i][k];
            float4 b0 = *(float4*)&Bs[k][tx * 8];
            float4 b1 = *(float4*)&Bs[k][tx * 8 + 4];
            b[0] = b0.x; b[1] = b0.y; b[2] = b0.z; b[3] = b0.w;
            b[4] = b1.x; b[5] = b1.y; b[6] = b1.z; b[7] = b1.w;
#pragma unroll
            for (int i = 0; i < 8; i++)
#pragma unroll
                for (int j = 0; j < 8; j++) acc[i][j] += a[i] * b[j];
        }
    }
}

// ---------------------------------------------------------------------------
// Kernel A: QKV GEMM + bias + per-head affine scatter
// ---------------------------------------------------------------------------
__device__ __forceinline__ void qkv_store_one(
    int b, int t, int n, float v,
    const float* __restrict__ q_scale, const float* __restrict__ q_bias,
    const float* __restrict__ k_scale, const float* __restrict__ k_bias)
{
    int sect = n >> 10, c = n & 1023;
    int h = c >> 6, d = c & 63;
    size_t idx = ((size_t)(b * NH_ + h) * T_ + t) * HD_ + d;
#if HAS_TCGEN05
    if (sect == 0)      g_q[idx] = tf32r(v * q_scale[c] + q_bias[c]);
    else if (sect == 1) g_k[idx] = tf32r(v * k_scale[c] + k_bias[c]);
    else                g_vT[((size_t)(b * NH_ + h) * HD_ + d) * T_ + t] = tf32r(v);
#else
    if (sect == 0)      g_q[idx] = v * q_scale[c] + q_bias[c];
    else if (sect == 1) g_k[idx] = v * k_scale[c] + k_bias[c];
    else                g_v[idx] = v;
#endif
}

__global__ __launch_bounds__(256)
void qkv_gemm_kernel(const float* __restrict__ X, const float* __restrict__ W,
                     const float* __restrict__ bias,
                     const float* __restrict__ q_scale, const float* __restrict__ q_bias,
                     const float* __restrict__ k_scale, const float* __restrict__ k_bias)
{
    extern __shared__ char smem[];
    const int bm = blockIdx.y * 128, bn = blockIdx.x * 128;
    const int tid = threadIdx.x;

#if HAS_TCGEN05
    uint32_t smb = smem_u32(smem);
    const int wid = tid >> 5, lid = tid & 31;
    if (wid == 0) {
        TCGEN05_ALLOC(smb, 128);
        TCGEN05_RELINQ();
    }
    if (tid == 0) { MBARRIER_INIT(smb + 16, 1); MBARRIER_INIT(smb + 24, 1); MBARRIER_INIT(smb + 32, 1); }
    __syncthreads();
    uint32_t tmem;
    asm volatile("ld.shared.b32 %0, [%1];" : "=r"(tmem) : "r"(smb));

    gemm_mainloop_tf32(g_xr, g_wqkvT, bm, bn, smb, tmem);

    if (wid < 4) {
        const int m = bm + wid * 32 + lid;
        const int b = m >> 11, t = m & 2047;
        const uint32_t woff = ((uint32_t)wid << 21);
#pragma unroll
        for (int chunk = 0; chunk < 4; chunk++) {
            uint32_t r[32];
            TCGEN05_LD_X32(r, tmem + chunk * 32 + woff);
            TCGEN05_WAIT_LD();
#pragma unroll
            for (int j = 0; j < 32; j++) {
                int n = bn + chunk * 32 + j;
                float v = __uint_as_float(r[j]) + bias[n];
                qkv_store_one(b, t, n, v, q_scale, q_bias, k_scale, k_bias);
            }
        }
    }
    __syncthreads();
    if (wid == 0) TCGEN05_DEALLOC(tmem, 128);
    (void)X; (void)W;
#else
    float acc[8][8];
#pragma unroll
    for (int i = 0; i < 8; i++)
#pragma unroll
        for (int j = 0; j < 8; j++) acc[i][j] = 0.f;
    gemm_mainloop_simt(X, W, 3072, bm, bn, smem, acc);
    const int tx = tid & 15, ty = tid >> 4;
#pragma unroll
    for (int i = 0; i < 8; i++) {
        int m = bm + ty * 8 + i;
        int b = m >> 11, t = m & 2047;
#pragma unroll
        for (int j = 0; j < 8; j++) {
            int n = bn + tx * 8 + j;
            qkv_store_one(b, t, n, acc[i][j] + bias[n], q_scale, q_bias, k_scale, k_bias);
        }
    }
#endif
}

// ---------------------------------------------------------------------------
// Kernel C: projection GEMM + bias -> out
// ---------------------------------------------------------------------------
__global__ __launch_bounds__(256)
void proj_gemm_kernel(const float* __restrict__ W, const float* __restrict__ bias,
                      float* __restrict__ out)
{
    extern __shared__ char smem[];
    const int bm = blockIdx.y * 128, bn = blockIdx.x * 128;
    const int tid = threadIdx.x;

#if HAS_TCGEN05
    uint32_t smb = smem_u32(smem);
    const int wid = tid >> 5, lid = tid & 31;
    if (wid == 0) {
        TCGEN05_ALLOC(smb, 128);
        TCGEN05_RELINQ();
    }
    if (tid == 0) { MBARRIER_INIT(smb + 16, 1); MBARRIER_INIT(smb + 24, 1); MBARRIER_INIT(smb + 32, 1); }
    __syncthreads();
    uint32_t tmem;
    asm volatile("ld.shared.b32 %0, [%1];" : "=r"(tmem) : "r"(smb));

    gemm_mainloop_tf32(g_y, g_wprojT, bm, bn, smb, tmem);

    if (wid < 4) {
        const int m = bm + wid * 32 + lid;
        const uint32_t woff = ((uint32_t)wid << 21);
#pragma unroll
        for (int chunk = 0; chunk < 4; chunk++) {
            uint32_t r[32];
            TCGEN05_LD_X32(r, tmem + chunk * 32 + woff);
            TCGEN05_WAIT_LD();
#pragma unroll
            for (int j = 0; j < 32; j++) {
                int n = bn + chunk * 32 + j;
                out[(size_t)m * 1024 + n] = __uint_as_float(r[j]) + bias[n];
            }
        }
    }
    __syncthreads();
    if (wid == 0) TCGEN05_DEALLOC(tmem, 128);
    (void)W;
#else
    float acc[8][8];
#pragma unroll
    for (int i = 0; i < 8; i++)
#pragma unroll
        for (int j = 0; j < 8; j++) acc[i][j] = 0.f;
    gemm_mainloop_simt(g_y, W, 1024, bm, bn, smem, acc);
    const int tx = tid & 15, ty = tid >> 4;
#pragma unroll
    for (int i = 0; i < 8; i++) {
        int m = bm + ty * 8 + i;
#pragma unroll
        for (int j = 0; j < 8; j++) {
            int n = bn + tx * 8 + j;
            out[(size_t)m * 1024 + n] = acc[i][j] + bias[n];
        }
    }
#endif
}

// ---------------------------------------------------------------------------
// Kernel B: causal flash attention — tcgen05 tf32, S-prefetch pipelined.
// CTA = 128 Q-rows x (b,h). 128 threads. grid (16, 64).
// TMEM: S double-buffered cols 0-63 / 64-127, O cols 128-191 (alloc 256).
// Smem: Q 32K | K 16K (single) | V 2x16K | P 32K | ctl. 114.8KB -> 2 CTAs/SM.
// ---------------------------------------------------------------------------
__global__ __launch_bounds__(128)
void attn_kernel()
{
#if HAS_TCGEN05
    extern __shared__ char smem[];
    uint32_t smb = smem_u32(smem);
    const int tid = threadIdx.x, wid = tid >> 5, lid = tid & 31;
    const int qt = gridDim.x - 1 - blockIdx.x;   // long CTAs first
    const int bh = blockIdx.y;

    const float* Qg  = g_q  + (size_t)bh * T_ * HD_;
    const float* Kg  = g_k  + (size_t)bh * T_ * HD_;
    const float* VTg = g_vT + (size_t)bh * HD_ * T_;

    const uint32_t Qb = smb + ATTN_Q;
    const uint32_t Kb = smb + ATTN_K;
    const uint32_t Vb = smb + ATTN_V;
    const uint32_t Pb = smb + ATTN_P;
    const uint32_t CT = smb + ATTN_CTL;       // tmem ptr
    const uint32_t MS = CT + 8;               // mbar for S commits
    const uint32_t MP = CT + 16;              // mbar for PV commits

    if (wid == 0) {
        TCGEN05_ALLOC(CT, 256);
        TCGEN05_RELINQ();
    }
    if (tid == 0) { MBARRIER_INIT(MS, 1); MBARRIER_INIT(MP, 1); }
    __syncthreads();
    uint32_t tmem;
    asm volatile("ld.shared.b32 %0, [%1];" : "=r"(tmem) : "r"(CT));

    const int nkt = 2 * qt + 2;

    // Q (128x64), K(0) (64x64), V(0) (64x64 d-major) loads
    for (int i = tid; i < 2048; i += 128) {
        int c = i >> 10, rem = i & 1023, r = rem >> 3, seg = rem & 7;
        cp_async16(Qb + c * 16384 + sw128((uint32_t)r * 128 + seg * 16),
                   Qg + (size_t)(qt * 128 + r) * 64 + c * 32 + seg * 4);
    }
    for (int i = tid; i < 1024; i += 128) {
        int c = i >> 9, rem = i & 511, r = rem >> 3, seg = rem & 7;
        uint32_t off = sw128((uint32_t)r * 128 + seg * 16);
        cp_async16(Kb + c * 8192 + off, Kg + (size_t)r * 64 + c * 32 + seg * 4);
        cp_async16(Vb + c * 8192 + off, VTg + (size_t)r * T_ + c * 32 + seg * 4);
    }
    CP_COMMIT();
    CP_WAIT0();
    __syncthreads();
    FENCE_ASYNC_SHARED();

    // issue S(0) -> S[0]
    if (wid == 0 && elect_one()) {
#pragma unroll
        for (int c = 0; c < 2; c++) {
            uint64_t ad = make_desc_sw128(Qb + c * 16384);
            uint64_t bd = make_desc_sw128(Kb + c * 8192);
#pragma unroll
            for (int s = 0; s < 4; s++)
                mma_tf32_ss(tmem, ad + s * 2, bd + s * 2, IDESC_ATT,
                            (c > 0 || s > 0) ? 1u : 0u);
        }
        TCGEN05_COMMIT(MS);
    }

    const int m = wid * 32 + lid;
    const int q_glob = qt * 128 + m;
    const uint32_t woff = ((uint32_t)wid << 21);

    float O[64];
#pragma unroll
    for (int j = 0; j < 64; j++) O[j] = 0.f;
    float mrow = -INFINITY, lrow = 0.f;

    for (int kt = 0; kt < nkt; kt++) {
        // 1. S(kt) complete (ran during previous iteration)
        MBARRIER_WAIT_PARITY(MS, (uint32_t)(kt & 1));
        TCGEN05_FENCE_AFTER();

        // 2. K buffer free (S(kt) consumed it): prefetch K(kt+1), V(kt+1)
        if (kt + 1 < nkt) {
            const uint32_t vb1 = Vb + ((uint32_t)(kt + 1) & 1) * 16384;
            for (int i = tid; i < 1024; i += 128) {
                int c = i >> 9, rem = i & 511, r = rem >> 3, seg = rem & 7;
                uint32_t off = sw128((uint32_t)r * 128 + seg * 16);
                cp_async16(Kb + c * 8192 + off,
                           Kg + (size_t)((kt + 1) * 64 + r) * 64 + c * 32 + seg * 4);
                cp_async16(vb1 + c * 8192 + off,
                           VTg + (size_t)r * T_ + (kt + 1) * 64 + c * 32 + seg * 4);
            }
        }
        CP_COMMIT();

        // 3. LDTM S(kt), softmax in-lane
        float sv[64];
        {
            const uint32_t Sb = tmem + ((uint32_t)(kt & 1)) * 64;
            uint32_t r0[32], r1[32];
            TCGEN05_LD_X32(r0, Sb + woff);
            TCGEN05_LD_X32(r1, Sb + 32 + woff);
            TCGEN05_WAIT_LD();
#pragma unroll
            for (int j = 0; j < 32; j++) { sv[j] = __uint_as_float(r0[j]); sv[32 + j] = __uint_as_float(r1[j]); }
        }
        const bool diag = (kt >= 2 * qt);
        float mt = -INFINITY;
#pragma unroll
        for (int j = 0; j < 64; j++) {
            float v = sv[j] * 0.125f;
            if (diag && (kt * 64 + j > q_glob)) v = -INFINITY;
            sv[j] = v;
            mt = fmaxf(mt, v);
        }
        float mn = fmaxf(mrow, mt);
        float rscale = __expf(mrow - mn);
        mrow = mn;
        float rs = 0.f;
#pragma unroll
        for (int j = 0; j < 64; j++) { float p = __expf(sv[j] - mn); sv[j] = p; rs += p; }
        lrow = lrow * rscale + rs;

        // 4. P -> smem (PV(kt-1) completed last iteration, buffer free)
#pragma unroll
        for (int j = 0; j < 64; j += 4) {
            float4 p4;
            p4.x = tf32r(sv[j]); p4.y = tf32r(sv[j + 1]);
            p4.z = tf32r(sv[j + 2]); p4.w = tf32r(sv[j + 3]);
            uint32_t c = (uint32_t)(j >> 5);
            uint32_t addr = Pb + c * 16384 + sw128((uint32_t)m * 128 + (uint32_t)(j & 31) * 4);
            asm volatile("st.shared.v4.b32 [%0], {%1,%2,%3,%4};"
                         :: "r"(addr), "r"(__float_as_uint(p4.x)), "r"(__float_as_uint(p4.y)),
                            "r"(__float_as_uint(p4.z)), "r"(__float_as_uint(p4.w)) : "memory");
        }
        FENCE_ASYNC_SHARED();
        __syncthreads();

        // 5. PV(kt): P x V[kt&1] -> O tmem (fresh each iter)
        if (wid == 0 && elect_one()) {
            const uint32_t vb = Vb + ((uint32_t)(kt & 1)) * 16384;
#pragma unroll
            for (int c = 0; c < 2; c++) {
                uint64_t ad = make_desc_sw128(Pb + c * 16384);
                uint64_t bd = make_desc_sw128(vb + c * 8192);
#pragma unroll
                for (int s = 0; s < 4; s++)
                    mma_tf32_ss(tmem + 128, ad + s * 2, bd + s * 2, IDESC_ATT,
                                (c > 0 || s > 0) ? 1u : 0u);
            }
            TCGEN05_COMMIT(MP);
        }

        // 6. issue S(kt+1) (K/V(kt+1) loads complete; overlaps PV + next softmax)
        if (kt + 1 < nkt) {
            CP_WAIT0();
            __syncthreads();
            FENCE_ASYNC_SHARED();
            if (wid == 0 && elect_one()) {
                const uint32_t Sb = tmem + ((uint32_t)((kt + 1) & 1)) * 64;
#pragma unroll
                for (int c = 0; c < 2; c++) {
                    uint64_t ad = make_desc_sw128(Qb + c * 16384);
                    uint64_t bd = make_desc_sw128(Kb + c * 8192);
#pragma unroll
                    for (int s = 0; s < 4; s++)
                        mma_tf32_ss(Sb, ad + s * 2, bd + s * 2, IDESC_ATT,
                                    (c > 0 || s > 0) ? 1u : 0u);
                }
                TCGEN05_COMMIT(MS);
            }
        }

        // 7. wait PV(kt), accumulate O with rescale
        MBARRIER_WAIT_PARITY(MP, (uint32_t)(kt & 1));
        TCGEN05_FENCE_AFTER();
        {
            uint32_t r0[32], r1[32];
            TCGEN05_LD_X32(r0, tmem + 128 + woff);
            TCGEN05_LD_X32(r1, tmem + 160 + woff);
            TCGEN05_WAIT_LD();
#pragma unroll
            for (int j = 0; j < 32; j++) {
                O[j]      = O[j]      * rscale + __uint_as_float(r0[j]);
                O[32 + j] = O[32 + j] * rscale + __uint_as_float(r1[j]);
            }
        }
    }

    // write O/l to g_y [B,T,C], tf32-rounded (feeds proj A)
    {
        const int b = bh >> 4, h = bh & 15;
        const int t = qt * 128 + m;
        float inv = 1.f / lrow;
        float* dst = &g_y[((size_t)(b * T_ + t)) * C_ + h * 64];
#pragma unroll
        for (int j = 0; j < 64; j += 4) {
            float4 o4;
            o4.x = tf32r(O[j] * inv);     o4.y = tf32r(O[j + 1] * inv);
            o4.z = tf32r(O[j + 2] * inv); o4.w = tf32r(O[j + 3] * inv);
            *(float4*)(dst + j) = o4;
        }
    }
    __syncthreads();
    if (wid == 0) TCGEN05_DEALLOC(tmem, 256);
#else
    // Fallback: correct SIMT flash attention, 128 threads, 1 q-row per thread.
    __shared__ float Ks[64][65];
    __shared__ float Vs[64][65];
    const int tid = threadIdx.x;
    const int qt = gridDim.x - 1 - blockIdx.x;
    const int bh = blockIdx.y;
    const int t = qt * 128 + tid;
    const float* Qg = g_q + (size_t)bh * T_ * HD_;
    const float* Kg = g_k + (size_t)bh * T_ * HD_;
    const float* Vg = g_v + (size_t)bh * T_ * HD_;

    float q[64], O[64];
#pragma unroll
    for (int d = 0; d < 64; d++) { q[d] = Qg[(size_t)t * 64 + d]; O[d] = 0.f; }
    float mrow = -INFINITY, lrow = 0.f;

    for (int kt = 0; kt < 2 * qt + 2; kt++) {
        __syncthreads();
        for (int i = tid; i < 64 * 64; i += 128) {
            int r = i >> 6, c = i & 63;
            Ks[r][c] = Kg[(size_t)(kt * 64 + r) * 64 + c];
            Vs[r][c] = Vg[(size_t)(kt * 64 + r) * 64 + c];
        }
        __syncthreads();
        for (int kk = 0; kk < 64; kk++) {
            int kg = kt * 64 + kk;
            if (kg > t) break;
            float s = 0.f;
#pragma unroll
            for (int d = 0; d < 64; d++) s += q[d] * Ks[kk][d];
            s *= 0.125f;
            float mn = fmaxf(mrow, s);
            float rscale = expf(mrow - mn);
            float p = expf(s - mn);
            lrow = lrow * rscale + p;
            mrow = mn;
#pragma unroll
            for (int d = 0; d < 64; d++) O[d] = O[d] * rscale + p * Vs[kk][d];
        }
    }
    const int b = bh >> 4, h = bh & 15;
    float inv = 1.f / lrow;
#pragma unroll
    for (int d = 0; d < 64; d++)
        g_y[((size_t)(b * T_ + t)) * C_ + h * 64 + d] = O[d] * inv;
#endif
}

// ---------------------------------------------------------------------------
extern "C" void kernel_launch(void* const* d_in, const int* in_sizes, int n_in,
                              void* d_out, int out_size)
{
    const float* x     = (const float*)d_in[0];
    const float* Wqkv  = (const float*)d_in[1];
    const float* bqkv  = (const float*)d_in[2];
    const float* Wproj = (const float*)d_in[3];
    const float* bproj = (const float*)d_in[4];
    const float* qsc   = (const float*)d_in[5];
    const float* qbi   = (const float*)d_in[6];
    const float* ksc   = (const float*)d_in[7];
    const float* kbi   = (const float*)d_in[8];
    float* out = (float*)d_out;
    (void)in_sizes; (void)n_in; (void)out_size;

    cudaFuncSetAttribute(qkv_gemm_kernel, cudaFuncAttributeMaxDynamicSharedMemorySize, GEMM_SMEM);
    cudaFuncSetAttribute(proj_gemm_kernel, cudaFuncAttributeMaxDynamicSharedMemorySize, GEMM_SMEM);
    cudaFuncSetAttribute(attn_kernel, cudaFuncAttributeMaxDynamicSharedMemorySize, ATTN_SMEM_T);

    float* p_xr;     cudaGetSymbolAddress((void**)&p_xr,     g_xr);
    float* p_wqkvT;  cudaGetSymbolAddress((void**)&p_wqkvT,  g_wqkvT);
    float* p_wprojT; cudaGetSymbolAddress((void**)&p_wprojT, g_wprojT);

    round_x_kernel<<<(M_ * C_ / 4 + 255) / 256, 256>>>(x, p_xr, M_ * C_ / 4);
    {
        dim3 gt(3072 / 32, 1024 / 32);
        transpose_round_kernel<<<gt, 256>>>(Wqkv, p_wqkvT, 1024, 3072);
    }
    {
        dim3 gt(1024 / 32, 1024 / 32);
        transpose_round_kernel<<<gt, 256>>>(Wproj, p_wprojT, 1024, 1024);
    }

    dim3 g1(3072 / 128, M_ / 128);   // 24 x 64
    qkv_gemm_kernel<<<g1, 256, GEMM_SMEM>>>(x, Wqkv, bqkv, qsc, qbi, ksc, kbi);

    dim3 g2(T_ / 128, BH_);          // 16 x 64
    attn_kernel<<<g2, 128, ATTN_SMEM_T>>>();

    dim3 g3(1024 / 128, M_ / 128);   // 8 x 64
    proj_gemm_kernel<<<g3, 256, GEMM_SMEM>>>(Wproj, bproj, out);
}